// round 1
// baseline (speedup 1.0000x reference)
#include <cuda_runtime.h>

// LSTM: B=4096, T=512, I=10, H=32, O=1. PyTorch gate order i,f,g,o.
// Mapping: 1 warp handles NB=4 batch elements; lane l owns hidden index l.
// Gates accumulated as packed f32x2 pairs (i,f) and (g,o) via fma.rn.f32x2.
// Weights rearranged in smem as [j][lane][gate] so ld.shared.v2.u64 yields
// both packed weight pairs directly. h/x broadcast via duplicated float2 in smem.

#define B_TOT 4096
#define T_LEN 512
#define I_DIM 10
#define H_DIM 32
#define NB 4

typedef unsigned long long u64;

__device__ __forceinline__ u64 fma2(u64 a, u64 b, u64 c) {
    u64 d;
    asm("fma.rn.f32x2 %0, %1, %2, %3;" : "=l"(d) : "l"(a), "l"(b), "l"(c));
    return d;
}
__device__ __forceinline__ u64 pack2(float lo, float hi) {
    u64 d;
    asm("mov.b64 %0, {%1, %2};" : "=l"(d) : "f"(lo), "f"(hi));
    return d;
}
__device__ __forceinline__ void unpack2(u64 v, float& lo, float& hi) {
    asm("mov.b64 {%0, %1}, %2;" : "=f"(lo), "=f"(hi) : "l"(v));
}
__device__ __forceinline__ float ex2f(float x) {
    float y; asm("ex2.approx.f32 %0, %1;" : "=f"(y) : "f"(x)); return y;
}
__device__ __forceinline__ float rcpf(float x) {
    float y; asm("rcp.approx.f32 %0, %1;" : "=f"(y) : "f"(x)); return y;
}
// sigmoid(x) = 1 / (1 + exp(-x)); exp(-x) = 2^(-x*log2e). ex2/rcp approx ~2^-22 rel err.
__device__ __forceinline__ float sigf(float x) {
    return rcpf(1.0f + ex2f(-1.4426950408889634f * x));
}
// tanh(x) = 2/(1+exp(-2x)) - 1. Saturates correctly: ex2->inf => rcp->0 => -1; ex2->0 => +1.
__device__ __forceinline__ float tanh_f(float x) {
    return fmaf(2.0f, rcpf(1.0f + ex2f(-2.8853900817779268f * x)), -1.0f);
}

__global__ __launch_bounds__(32, 16) void lstm_warp_kernel(
    const float* __restrict__ x,    // [B, T, I]
    const float* __restrict__ Wih,  // [4H, I]
    const float* __restrict__ Whh,  // [4H, H]
    const float* __restrict__ bih,  // [4H]
    const float* __restrict__ bhh,  // [4H]
    const float* __restrict__ Wd,   // [O=1, H]
    const float* __restrict__ bd,   // [O=1]
    float* __restrict__ out)        // [B, 1]
{
    // Rearranged recurrent weights: sWr[(j*32+l)*4 + q] = Whh[q*32+l][j]
    // => float4 per (j,lane) = (W_i, W_f, W_g, W_o); u64 pairs align with (i,f) and (g,o).
    __shared__ float sWr[H_DIM * 32 * 4];   // 16 KB
    __shared__ float sWx[I_DIM * 32 * 4];   // 5 KB
    __shared__ float2 hdup[NB][H_DIM];      // duplicated (h,h) pairs for broadcast LDS.64
    __shared__ float2 xdup[NB][16];         // duplicated (x,x) pairs (10 used, padded)

    const int lane = threadIdx.x;
    const int b0 = blockIdx.x * NB;

    // Load + rearrange weights (block-local; data is L2-resident across blocks).
    for (int flat = lane; flat < H_DIM * 32 * 4; flat += 32) {
        int q = flat & 3, l2 = (flat >> 2) & 31, j = flat >> 7;
        sWr[flat] = Whh[(q * 32 + l2) * H_DIM + j];
    }
    for (int flat = lane; flat < I_DIM * 32 * 4; flat += 32) {
        int q = flat & 3, l2 = (flat >> 2) & 31, i = flat >> 7;
        sWx[flat] = Wih[(q * 32 + l2) * I_DIM + i];
    }
    // Fused bias (b_ih + b_hh), packed per gate-pair, kept in registers.
    const u64 bias_if = pack2(bih[0 * 32 + lane] + bhh[0 * 32 + lane],
                              bih[1 * 32 + lane] + bhh[1 * 32 + lane]);
    const u64 bias_go = pack2(bih[2 * 32 + lane] + bhh[2 * 32 + lane],
                              bih[3 * 32 + lane] + bhh[3 * 32 + lane]);
    __syncwarp();

    float h[NB], c[NB], xv[NB];
#pragma unroll
    for (int k = 0; k < NB; k++) { h[k] = 0.0f; c[k] = 0.0f; xv[k] = 0.0f; }

    // Preload x[t=0]
    if (lane < I_DIM) {
#pragma unroll
        for (int k = 0; k < NB; k++)
            xv[k] = x[((b0 + k) * T_LEN + 0) * I_DIM + lane];
    }

    for (int t = 0; t < T_LEN; t++) {
        // Publish current h and x as duplicated pairs.
#pragma unroll
        for (int k = 0; k < NB; k++)
            hdup[k][lane] = make_float2(h[k], h[k]);
        if (lane < I_DIM) {
#pragma unroll
            for (int k = 0; k < NB; k++)
                xdup[k][lane] = make_float2(xv[k], xv[k]);
        }
        __syncwarp();

        // Prefetch next timestep's x (clamped; overlaps with gate compute).
        const int t2 = (t + 1 < T_LEN) ? (t + 1) : (T_LEN - 1);
        if (lane < I_DIM) {
#pragma unroll
            for (int k = 0; k < NB; k++)
                xv[k] = x[((b0 + k) * T_LEN + t2) * I_DIM + lane];
        }

        u64 aif[NB], ago[NB];
#pragma unroll
        for (int k = 0; k < NB; k++) { aif[k] = bias_if; ago[k] = bias_go; }

        // Input contribution: 10 x-values.
#pragma unroll
        for (int i = 0; i < I_DIM; i++) {
            const ulonglong2 w = *(const ulonglong2*)&sWx[(i * 32 + lane) * 4];
#pragma unroll
            for (int k = 0; k < NB; k++) {
                const u64 xp = *(const u64*)&xdup[k][i];
                aif[k] = fma2(w.x, xp, aif[k]);
                ago[k] = fma2(w.y, xp, ago[k]);
            }
        }
        // Recurrent contribution: 32 h-values.
#pragma unroll
        for (int j = 0; j < H_DIM; j++) {
            const ulonglong2 w = *(const ulonglong2*)&sWr[(j * 32 + lane) * 4];
#pragma unroll
            for (int k = 0; k < NB; k++) {
                const u64 hp = *(const u64*)&hdup[k][j];
                aif[k] = fma2(w.x, hp, aif[k]);
                ago[k] = fma2(w.y, hp, ago[k]);
            }
        }

        // Activations + state update.
#pragma unroll
        for (int k = 0; k < NB; k++) {
            float ai, af, ag, ao;
            unpack2(aif[k], ai, af);
            unpack2(ago[k], ag, ao);
            const float ig = sigf(ai);
            const float fg = sigf(af);
            const float gg = tanh_f(ag);
            const float og = sigf(ao);
            c[k] = fmaf(fg, c[k], ig * gg);
            h[k] = og * tanh_f(c[k]);
        }
        __syncwarp();  // all lanes done reading hdup/xdup before next overwrite
    }

    // Final dense: out[b] = sum_l h[b][l] * Wd[l] + bd  (O = 1)
    const float wd = Wd[lane];
    const float bdv = bd[0];
#pragma unroll
    for (int k = 0; k < NB; k++) {
        float p = h[k] * wd;
#pragma unroll
        for (int off = 16; off; off >>= 1)
            p += __shfl_xor_sync(0xffffffffu, p, off);
        if (lane == 0) out[b0 + k] = p + bdv;
    }
}

extern "C" void kernel_launch(void* const* d_in, const int* in_sizes, int n_in,
                              void* d_out, int out_size) {
    const float* x   = (const float*)d_in[0];
    const float* Wih = (const float*)d_in[1];
    const float* Whh = (const float*)d_in[2];
    const float* bih = (const float*)d_in[3];
    const float* bhh = (const float*)d_in[4];
    const float* Wd  = (const float*)d_in[5];
    const float* bd  = (const float*)d_in[6];
    (void)in_sizes; (void)n_in; (void)out_size;

    lstm_warp_kernel<<<B_TOT / NB, 32>>>(x, Wih, Whh, bih, bhh, Wd, bd,
                                         (float*)d_out);
}

// round 2
// speedup vs baseline: 1.1375x; 1.1375x over previous
#include <cuda_runtime.h>

// LSTM: B=4096, T=512, I=10, H=32, O=1. Gate order i,f,g,o.
// 1 warp = NB=4 batch elements; lane l owns hidden index l.
// Recurrent weights live in REGISTERS as f32x2 pairs over j (even/odd halves
// of each accumulator hold even-j / odd-j partial sums; summed at the end).
// h is broadcast via uniform LDS.128 from compact smem (no duplication).

#define B_TOT 4096
#define T_LEN 512
#define I_DIM 10
#define H_DIM 32
#define NB 4
#define NPH 16   // h pairs (32/2)
#define NPX 5    // x pairs (10/2)

typedef unsigned long long u64;

__device__ __forceinline__ u64 fma2(u64 a, u64 b, u64 c) {
    u64 d;
    asm("fma.rn.f32x2 %0, %1, %2, %3;" : "=l"(d) : "l"(a), "l"(b), "l"(c));
    return d;
}
__device__ __forceinline__ u64 pack2(float lo, float hi) {
    u64 d;
    asm("mov.b64 %0, {%1, %2};" : "=l"(d) : "f"(lo), "f"(hi));
    return d;
}
__device__ __forceinline__ void unpack2(u64 v, float& lo, float& hi) {
    asm("mov.b64 {%0, %1}, %2;" : "=f"(lo), "=f"(hi) : "l"(v));
}
__device__ __forceinline__ float ex2f(float x) {
    float y; asm("ex2.approx.f32 %0, %1;" : "=f"(y) : "f"(x)); return y;
}
__device__ __forceinline__ float rcpf(float x) {
    float y; asm("rcp.approx.f32 %0, %1;" : "=f"(y) : "f"(x)); return y;
}
__device__ __forceinline__ float sigf(float x) {
    return rcpf(1.0f + ex2f(-1.4426950408889634f * x));
}
__device__ __forceinline__ float tanh_f(float x) {
    return fmaf(2.0f, rcpf(1.0f + ex2f(-2.8853900817779268f * x)), -1.0f);
}

__global__ __launch_bounds__(32, 8) void lstm_warp_kernel(
    const float* __restrict__ x,    // [B, T, I]
    const float* __restrict__ Wih,  // [4H, I]
    const float* __restrict__ Whh,  // [4H, H]
    const float* __restrict__ bih,  // [4H]
    const float* __restrict__ bhh,  // [4H]
    const float* __restrict__ Wd,   // [1, H]
    const float* __restrict__ bd,   // [1]
    float* __restrict__ out)        // [B, 1]
{
    // x-weights: per (pair p, lane l): (w_i pair, w_f pair) and (w_g, w_o) as 16B.
    __shared__ ulonglong2 sWx_if[NPX][32];   // 2.5 KB
    __shared__ ulonglong2 sWx_go[NPX][32];   // 2.5 KB
    __shared__ __align__(16) float sH[NB][H_DIM];
    __shared__ __align__(16) float sX[NB][I_DIM];

    const int lane = threadIdx.x;
    const int b0 = blockIdx.x * NB;

    // ---- Prologue: recurrent weights into registers (paired over j) ----
    u64 whi[NPH], whf[NPH], whg[NPH], who[NPH];
#pragma unroll
    for (int p = 0; p < NPH; p++) {
        whi[p] = *(const u64*)&Whh[(0 * 32 + lane) * H_DIM + 2 * p];
        whf[p] = *(const u64*)&Whh[(1 * 32 + lane) * H_DIM + 2 * p];
        whg[p] = *(const u64*)&Whh[(2 * 32 + lane) * H_DIM + 2 * p];
        who[p] = *(const u64*)&Whh[(3 * 32 + lane) * H_DIM + 2 * p];
    }
    // x-weights into smem (each lane builds its own column).
#pragma unroll
    for (int p = 0; p < NPX; p++) {
        ulonglong2 v;
        v.x = pack2(Wih[(0 * 32 + lane) * I_DIM + 2 * p], Wih[(0 * 32 + lane) * I_DIM + 2 * p + 1]);
        v.y = pack2(Wih[(1 * 32 + lane) * I_DIM + 2 * p], Wih[(1 * 32 + lane) * I_DIM + 2 * p + 1]);
        sWx_if[p][lane] = v;
        v.x = pack2(Wih[(2 * 32 + lane) * I_DIM + 2 * p], Wih[(2 * 32 + lane) * I_DIM + 2 * p + 1]);
        v.y = pack2(Wih[(3 * 32 + lane) * I_DIM + 2 * p], Wih[(3 * 32 + lane) * I_DIM + 2 * p + 1]);
        sWx_go[p][lane] = v;
    }
    const float bias_i = bih[0 * 32 + lane] + bhh[0 * 32 + lane];
    const float bias_f = bih[1 * 32 + lane] + bhh[1 * 32 + lane];
    const float bias_g = bih[2 * 32 + lane] + bhh[2 * 32 + lane];
    const float bias_o = bih[3 * 32 + lane] + bhh[3 * 32 + lane];
    __syncwarp();

    float h[NB], c[NB], xv[NB];
#pragma unroll
    for (int k = 0; k < NB; k++) { h[k] = 0.0f; c[k] = 0.0f; xv[k] = 0.0f; }

    if (lane < I_DIM) {
#pragma unroll
        for (int k = 0; k < NB; k++)
            xv[k] = x[((b0 + k) * T_LEN + 0) * I_DIM + lane];
    }

    for (int t = 0; t < T_LEN; t++) {
        // Publish compact h and x.
#pragma unroll
        for (int k = 0; k < NB; k++)
            sH[k][lane] = h[k];
        if (lane < I_DIM) {
#pragma unroll
            for (int k = 0; k < NB; k++)
                sX[k][lane] = xv[k];
        }
        __syncwarp();

        // Prefetch next timestep's x (overlaps with gate compute).
        const int t2 = (t + 1 < T_LEN) ? (t + 1) : (T_LEN - 1);
        if (lane < I_DIM) {
#pragma unroll
            for (int k = 0; k < NB; k++)
                xv[k] = x[((b0 + k) * T_LEN + t2) * I_DIM + lane];
        }

        // Accumulators: lo half = even-j sum, hi half = odd-j sum.
        u64 ai[NB], af[NB], ag[NB], ao[NB];
#pragma unroll
        for (int k = 0; k < NB; k++) { ai[k] = 0; af[k] = 0; ag[k] = 0; ao[k] = 0; }

        // Recurrent part: register weights x uniform-broadcast h pairs.
#pragma unroll
        for (int k = 0; k < NB; k++) {
#pragma unroll
            for (int pp = 0; pp < 8; pp++) {
                const ulonglong2 hp = *(const ulonglong2*)&sH[k][4 * pp];
                ai[k] = fma2(whi[2 * pp], hp.x, ai[k]);
                af[k] = fma2(whf[2 * pp], hp.x, af[k]);
                ag[k] = fma2(whg[2 * pp], hp.x, ag[k]);
                ao[k] = fma2(who[2 * pp], hp.x, ao[k]);
                ai[k] = fma2(whi[2 * pp + 1], hp.y, ai[k]);
                af[k] = fma2(whf[2 * pp + 1], hp.y, af[k]);
                ag[k] = fma2(whg[2 * pp + 1], hp.y, ag[k]);
                ao[k] = fma2(who[2 * pp + 1], hp.y, ao[k]);
            }
        }
        // Input part: p-outer so only 4 weight u64s live at a time.
#pragma unroll
        for (int p = 0; p < NPX; p++) {
            const ulonglong2 wif = sWx_if[p][lane];
            const ulonglong2 wgo = sWx_go[p][lane];
#pragma unroll
            for (int k = 0; k < NB; k++) {
                const u64 xp = *(const u64*)&sX[k][2 * p];
                ai[k] = fma2(wif.x, xp, ai[k]);
                af[k] = fma2(wif.y, xp, af[k]);
                ag[k] = fma2(wgo.x, xp, ag[k]);
                ao[k] = fma2(wgo.y, xp, ao[k]);
            }
        }

        // Activations + state update.
#pragma unroll
        for (int k = 0; k < NB; k++) {
            float lo, hi;
            unpack2(ai[k], lo, hi); const float gi = sigf(lo + hi + bias_i);
            unpack2(af[k], lo, hi); const float gf = sigf(lo + hi + bias_f);
            unpack2(ag[k], lo, hi); const float gg = tanh_f(lo + hi + bias_g);
            unpack2(ao[k], lo, hi); const float go = sigf(lo + hi + bias_o);
            c[k] = fmaf(gf, c[k], gi * gg);
            h[k] = go * tanh_f(c[k]);
        }
        __syncwarp();
    }

    // Final dense: out[b] = sum_l h[b][l] * Wd[l] + bd
    const float wd = Wd[lane];
    const float bdv = bd[0];
#pragma unroll
    for (int k = 0; k < NB; k++) {
        float p = h[k] * wd;
#pragma unroll
        for (int off = 16; off; off >>= 1)
            p += __shfl_xor_sync(0xffffffffu, p, off);
        if (lane == 0) out[b0 + k] = p + bdv;
    }
}

extern "C" void kernel_launch(void* const* d_in, const int* in_sizes, int n_in,
                              void* d_out, int out_size) {
    const float* x   = (const float*)d_in[0];
    const float* Wih = (const float*)d_in[1];
    const float* Whh = (const float*)d_in[2];
    const float* bih = (const float*)d_in[3];
    const float* bhh = (const float*)d_in[4];
    const float* Wd  = (const float*)d_in[5];
    const float* bd  = (const float*)d_in[6];
    (void)in_sizes; (void)n_in; (void)out_size;

    lstm_warp_kernel<<<B_TOT / NB, 32>>>(x, Wih, Whh, bih, bhh, Wd, bd,
                                         (float*)d_out);
}